// round 6
// baseline (speedup 1.0000x reference)
#include <cuda_runtime.h>
#include <math.h>

#define D 4096
#define TWO_D 8192
#define THREADS 256
#define NWARPS (THREADS / 32)
#define MAX_GRID (148 * 8)

__device__ double              g_sum   = 0.0;
__device__ unsigned long long  g_count = 0ull;
__device__ unsigned int        g_done  = 0u;

__global__ __launch_bounds__(THREADS) void fused_kernel(
    const float* __restrict__ outp,
    const float* __restrict__ gtp,
    const int*   __restrict__ epochp,
    float*       __restrict__ res,
    int rows)
{
    __shared__ float s_sum[NWARPS];
    __shared__ float s_max[NWARPS];
    __shared__ float s_gv[NWARPS];  __shared__ int s_gi[NWARPS];
    __shared__ float s_ov[NWARPS];  __shared__ int s_oi[NWARPS];

    const int lane = threadIdx.x & 31;
    const int wid  = threadIdx.x >> 5;

    // block-local accumulators (only thread 0's copies are used)
    double             blk_sum = 0.0;
    unsigned long long blk_cnt = 0ull;

    float e_thresh = 0.5f;
    if (threadIdx.x == 0) {
        int e = *epochp;
        e_thresh = (e % 10 == 0) ? (float)(0.5 * exp(-0.2)) : 0.5f;
    }

    for (int row = blockIdx.x; row < rows; row += gridDim.x) {
        const size_t base = (size_t)row * TWO_D;
        const float4* __restrict__ out_r = (const float4*)(outp + base);
        const float4* __restrict__ out_i = (const float4*)(outp + base + D);
        const float4* __restrict__ gt_r  = (const float4*)(gtp + base);
        const float4* __restrict__ gt_i  = (const float4*)(gtp + base + D);

        float sum   = 0.0f;
        float maxsq = 0.0f;
        float gmax  = -INFINITY; int gidx = 0;
        float omax  = -INFINITY; int oidx = 0;

        #pragma unroll 4
        for (int j = threadIdx.x; j < D / 4; j += THREADS) {
            float4 or4 = out_r[j];
            float4 gr4 = gt_r[j];
            float4 oi4 = out_i[j];
            float4 gi4 = gt_i[j];

            float orv[4] = {or4.x, or4.y, or4.z, or4.w};
            float grv[4] = {gr4.x, gr4.y, gr4.z, gr4.w};
            float oiv[4] = {oi4.x, oi4.y, oi4.z, oi4.w};
            float giv[4] = {gi4.x, gi4.y, gi4.z, gi4.w};

            #pragma unroll
            for (int k = 0; k < 4; k++) {
                float er = grv[k] - orv[k];
                float ei = giv[k] - oiv[k];
                float sq = er * er + ei * ei;
                sum += sq;
                maxsq = fmaxf(maxsq, sq);
                int idx = j * 4 + k;
                if (grv[k] > gmax) { gmax = grv[k]; gidx = idx; }
                if (orv[k] > omax) { omax = orv[k]; oidx = idx; }
            }
        }

        // ---- warp reduction ----
        #pragma unroll
        for (int off = 16; off > 0; off >>= 1) {
            sum   += __shfl_down_sync(0xffffffff, sum, off);
            maxsq  = fmaxf(maxsq, __shfl_down_sync(0xffffffff, maxsq, off));
            float gv = __shfl_down_sync(0xffffffff, gmax, off);
            int   gi = __shfl_down_sync(0xffffffff, gidx, off);
            if (gv > gmax || (gv == gmax && gi < gidx)) { gmax = gv; gidx = gi; }
            float ov = __shfl_down_sync(0xffffffff, omax, off);
            int   oi = __shfl_down_sync(0xffffffff, oidx, off);
            if (ov > omax || (ov == omax && oi < oidx)) { omax = ov; oidx = oi; }
        }

        if (lane == 0) {
            s_sum[wid] = sum;  s_max[wid] = maxsq;
            s_gv[wid] = gmax;  s_gi[wid] = gidx;
            s_ov[wid] = omax;  s_oi[wid] = oidx;
        }
        __syncthreads();

        if (threadIdx.x == 0) {
            float tsum = s_sum[0], tmax = s_max[0];
            float tgv = s_gv[0]; int tgi = s_gi[0];
            float tov = s_ov[0]; int toi = s_oi[0];
            #pragma unroll
            for (int w = 1; w < NWARPS; w++) {
                tsum += s_sum[w];
                tmax = fmaxf(tmax, s_max[w]);
                if (s_gv[w] > tgv || (s_gv[w] == tgv && s_gi[w] < tgi)) { tgv = s_gv[w]; tgi = s_gi[w]; }
                if (s_ov[w] > tov || (s_ov[w] == tov && s_oi[w] < toi)) { tov = s_ov[w]; toi = s_oi[w]; }
            }

            float e_max = sqrtf(tmax);
            bool masked = (tgi == toi) && (e_max < e_thresh);

            if (!masked) blk_sum += (double)tsum;
            blk_cnt += masked ? 1ull : (unsigned long long)D;
        }
        __syncthreads();   // protect shared arrays before next row's writes
    }

    // ---- one atomic pair per block, then last-block finalization ----
    if (threadIdx.x == 0) {
        atomicAdd(&g_sum, blk_sum);
        atomicAdd(&g_count, blk_cnt);
        __threadfence();
        unsigned int ticket = atomicAdd(&g_done, 1u);
        if (ticket == gridDim.x - 1) {
            // all other blocks' atomics are visible (fence + atomic ordering)
            double s = *((volatile double*)&g_sum);
            unsigned long long c = *((volatile unsigned long long*)&g_count);
            res[0] = (float)(s / (1.0 + (double)c));
            // reset for the next graph replay (deterministic re-execution)
            g_sum   = 0.0;
            g_count = 0ull;
            g_done  = 0u;
        }
    }
}

extern "C" void kernel_launch(void* const* d_in, const int* in_sizes, int n_in,
                              void* d_out, int out_size) {
    const float* outp   = (const float*)d_in[0];
    const float* gtp    = (const float*)d_in[1];
    const int*   epochp = (const int*)d_in[2];
    float* res = (float*)d_out;

    int rows = in_sizes[0] / TWO_D;   // 16384
    int grid = rows < MAX_GRID ? rows : MAX_GRID;

    fused_kernel<<<grid, THREADS>>>(outp, gtp, epochp, res, rows);
}

// round 7
// speedup vs baseline: 1.0552x; 1.0552x over previous
#include <cuda_runtime.h>
#include <math.h>

#define D 4096
#define TWO_D 8192
#define THREADS 256
#define NWARPS (THREADS / 32)

__device__ double              g_sum   = 0.0;
__device__ unsigned long long  g_count = 0ull;
__device__ unsigned int        g_done  = 0u;

__global__ __launch_bounds__(THREADS) void fused_row_kernel(
    const float* __restrict__ outp,
    const float* __restrict__ gtp,
    const int*   __restrict__ epochp,
    float*       __restrict__ res)
{
    const int row = blockIdx.x;
    const size_t base = (size_t)row * TWO_D;
    const float4* __restrict__ out_r = (const float4*)(outp + base);
    const float4* __restrict__ out_i = (const float4*)(outp + base + D);
    const float4* __restrict__ gt_r  = (const float4*)(gtp + base);
    const float4* __restrict__ gt_i  = (const float4*)(gtp + base + D);

    float sum   = 0.0f;
    float maxsq = 0.0f;
    float gmax  = -INFINITY; int gidx = 0;
    float omax  = -INFINITY; int oidx = 0;

    #pragma unroll 4
    for (int j = threadIdx.x; j < D / 4; j += THREADS) {
        float4 or4 = out_r[j];
        float4 gr4 = gt_r[j];
        float4 oi4 = out_i[j];
        float4 gi4 = gt_i[j];

        float orv[4] = {or4.x, or4.y, or4.z, or4.w};
        float grv[4] = {gr4.x, gr4.y, gr4.z, gr4.w};
        float oiv[4] = {oi4.x, oi4.y, oi4.z, oi4.w};
        float giv[4] = {gi4.x, gi4.y, gi4.z, gi4.w};

        #pragma unroll
        for (int k = 0; k < 4; k++) {
            float er = grv[k] - orv[k];
            float ei = giv[k] - oiv[k];
            float sq = er * er + ei * ei;
            sum += sq;
            maxsq = fmaxf(maxsq, sq);
            int idx = j * 4 + k;
            if (grv[k] > gmax) { gmax = grv[k]; gidx = idx; }
            if (orv[k] > omax) { omax = orv[k]; oidx = idx; }
        }
    }

    // ---- warp reduction ----
    #pragma unroll
    for (int off = 16; off > 0; off >>= 1) {
        sum   += __shfl_down_sync(0xffffffff, sum, off);
        maxsq  = fmaxf(maxsq, __shfl_down_sync(0xffffffff, maxsq, off));
        float gv = __shfl_down_sync(0xffffffff, gmax, off);
        int   gi = __shfl_down_sync(0xffffffff, gidx, off);
        if (gv > gmax || (gv == gmax && gi < gidx)) { gmax = gv; gidx = gi; }
        float ov = __shfl_down_sync(0xffffffff, omax, off);
        int   oi = __shfl_down_sync(0xffffffff, oidx, off);
        if (ov > omax || (ov == omax && oi < oidx)) { omax = ov; oidx = oi; }
    }

    // ---- block reduction across warps ----
    __shared__ float s_sum[NWARPS];
    __shared__ float s_max[NWARPS];
    __shared__ float s_gv[NWARPS];  __shared__ int s_gi[NWARPS];
    __shared__ float s_ov[NWARPS];  __shared__ int s_oi[NWARPS];

    int lane = threadIdx.x & 31;
    int wid  = threadIdx.x >> 5;
    if (lane == 0) {
        s_sum[wid] = sum;  s_max[wid] = maxsq;
        s_gv[wid] = gmax;  s_gi[wid] = gidx;
        s_ov[wid] = omax;  s_oi[wid] = oidx;
    }
    __syncthreads();

    if (threadIdx.x == 0) {
        float tsum = s_sum[0], tmax = s_max[0];
        float tgv = s_gv[0]; int tgi = s_gi[0];
        float tov = s_ov[0]; int toi = s_oi[0];
        #pragma unroll
        for (int w = 1; w < NWARPS; w++) {
            tsum += s_sum[w];
            tmax = fmaxf(tmax, s_max[w]);
            if (s_gv[w] > tgv || (s_gv[w] == tgv && s_gi[w] < tgi)) { tgv = s_gv[w]; tgi = s_gi[w]; }
            if (s_ov[w] > tov || (s_ov[w] == tov && s_oi[w] < toi)) { tov = s_ov[w]; toi = s_oi[w]; }
        }

        int e = *epochp;
        float e_thresh = (e % 10 == 0) ? (float)(0.5 * exp(-0.2)) : 0.5f;
        float e_max = sqrtf(tmax);
        bool masked = (tgi == toi) && (e_max < e_thresh);

        if (!masked) atomicAdd(&g_sum, (double)tsum);
        atomicAdd(&g_count, masked ? 1ull : (unsigned long long)D);

        // ---- last-block finalization (replaces separate finalize launch) ----
        __threadfence();
        unsigned int ticket = atomicAdd(&g_done, 1u);
        if (ticket == gridDim.x - 1) {
            double s = *((volatile double*)&g_sum);
            unsigned long long c = *((volatile unsigned long long*)&g_count);
            res[0] = (float)(s / (1.0 + (double)c));
            // reset for the next graph replay (deterministic re-execution)
            g_sum   = 0.0;
            g_count = 0ull;
            g_done  = 0u;
        }
    }
}

extern "C" void kernel_launch(void* const* d_in, const int* in_sizes, int n_in,
                              void* d_out, int out_size) {
    const float* outp   = (const float*)d_in[0];
    const float* gtp    = (const float*)d_in[1];
    const int*   epochp = (const int*)d_in[2];
    float* res = (float*)d_out;

    int rows = in_sizes[0] / TWO_D;   // 16384

    fused_row_kernel<<<rows, THREADS>>>(outp, gtp, epochp, res);
}

// round 8
// speedup vs baseline: 1.0688x; 1.0129x over previous
#include <cuda_runtime.h>
#include <math.h>

#define D 4096
#define TWO_D 8192
#define THREADS 128
#define NWARPS (THREADS / 32)

__device__ double              g_sum   = 0.0;
__device__ unsigned long long  g_count = 0ull;
__device__ unsigned int        g_done  = 0u;

__global__ __launch_bounds__(THREADS) void fused_row_kernel(
    const float* __restrict__ outp,
    const float* __restrict__ gtp,
    const int*   __restrict__ epochp,
    float*       __restrict__ res)
{
    const int row = blockIdx.x;
    const size_t base = (size_t)row * TWO_D;
    const float4* __restrict__ out_r = (const float4*)(outp + base);
    const float4* __restrict__ out_i = (const float4*)(outp + base + D);
    const float4* __restrict__ gt_r  = (const float4*)(gtp + base);
    const float4* __restrict__ gt_i  = (const float4*)(gtp + base + D);

    float sum   = 0.0f;
    float maxsq = 0.0f;
    float gmax  = -INFINITY; int gidx = 0;
    float omax  = -INFINITY; int oidx = 0;

    #pragma unroll 4
    for (int j = threadIdx.x; j < D / 4; j += THREADS) {
        float4 or4 = __ldcs(&out_r[j]);
        float4 gr4 = __ldcs(&gt_r[j]);
        float4 oi4 = __ldcs(&out_i[j]);
        float4 gi4 = __ldcs(&gt_i[j]);

        float orv[4] = {or4.x, or4.y, or4.z, or4.w};
        float grv[4] = {gr4.x, gr4.y, gr4.z, gr4.w};
        float oiv[4] = {oi4.x, oi4.y, oi4.z, oi4.w};
        float giv[4] = {gi4.x, gi4.y, gi4.z, gi4.w};

        #pragma unroll
        for (int k = 0; k < 4; k++) {
            float er = grv[k] - orv[k];
            float ei = giv[k] - oiv[k];
            float sq = er * er + ei * ei;
            sum += sq;
            maxsq = fmaxf(maxsq, sq);
            int idx = j * 4 + k;
            if (grv[k] > gmax) { gmax = grv[k]; gidx = idx; }
            if (orv[k] > omax) { omax = orv[k]; oidx = idx; }
        }
    }

    // ---- warp reduction ----
    #pragma unroll
    for (int off = 16; off > 0; off >>= 1) {
        sum   += __shfl_down_sync(0xffffffff, sum, off);
        maxsq  = fmaxf(maxsq, __shfl_down_sync(0xffffffff, maxsq, off));
        float gv = __shfl_down_sync(0xffffffff, gmax, off);
        int   gi = __shfl_down_sync(0xffffffff, gidx, off);
        if (gv > gmax || (gv == gmax && gi < gidx)) { gmax = gv; gidx = gi; }
        float ov = __shfl_down_sync(0xffffffff, omax, off);
        int   oi = __shfl_down_sync(0xffffffff, oidx, off);
        if (ov > omax || (ov == omax && oi < oidx)) { omax = ov; oidx = oi; }
    }

    // ---- block reduction across warps ----
    __shared__ float s_sum[NWARPS];
    __shared__ float s_max[NWARPS];
    __shared__ float s_gv[NWARPS];  __shared__ int s_gi[NWARPS];
    __shared__ float s_ov[NWARPS];  __shared__ int s_oi[NWARPS];

    int lane = threadIdx.x & 31;
    int wid  = threadIdx.x >> 5;
    if (lane == 0) {
        s_sum[wid] = sum;  s_max[wid] = maxsq;
        s_gv[wid] = gmax;  s_gi[wid] = gidx;
        s_ov[wid] = omax;  s_oi[wid] = oidx;
    }
    __syncthreads();

    if (threadIdx.x == 0) {
        float tsum = s_sum[0], tmax = s_max[0];
        float tgv = s_gv[0]; int tgi = s_gi[0];
        float tov = s_ov[0]; int toi = s_oi[0];
        #pragma unroll
        for (int w = 1; w < NWARPS; w++) {
            tsum += s_sum[w];
            tmax = fmaxf(tmax, s_max[w]);
            if (s_gv[w] > tgv || (s_gv[w] == tgv && s_gi[w] < tgi)) { tgv = s_gv[w]; tgi = s_gi[w]; }
            if (s_ov[w] > tov || (s_ov[w] == tov && s_oi[w] < toi)) { tov = s_ov[w]; toi = s_oi[w]; }
        }

        int e = *epochp;
        float e_thresh = (e % 10 == 0) ? (float)(0.5 * exp(-0.2)) : 0.5f;
        float e_max = sqrtf(tmax);
        bool masked = (tgi == toi) && (e_max < e_thresh);

        if (!masked) atomicAdd(&g_sum, (double)tsum);
        atomicAdd(&g_count, masked ? 1ull : (unsigned long long)D);

        // ---- last-block finalization ----
        __threadfence();
        unsigned int ticket = atomicAdd(&g_done, 1u);
        if (ticket == gridDim.x - 1) {
            double s = *((volatile double*)&g_sum);
            unsigned long long c = *((volatile unsigned long long*)&g_count);
            res[0] = (float)(s / (1.0 + (double)c));
            // reset for the next graph replay (deterministic re-execution)
            g_sum   = 0.0;
            g_count = 0ull;
            g_done  = 0u;
        }
    }
}

extern "C" void kernel_launch(void* const* d_in, const int* in_sizes, int n_in,
                              void* d_out, int out_size) {
    const float* outp   = (const float*)d_in[0];
    const float* gtp    = (const float*)d_in[1];
    const int*   epochp = (const int*)d_in[2];
    float* res = (float*)d_out;

    int rows = in_sizes[0] / TWO_D;   // 16384

    fused_row_kernel<<<rows, THREADS>>>(outp, gtp, epochp, res);
}